// round 1
// baseline (speedup 1.0000x reference)
#include <cuda_runtime.h>
#include <cuda_bf16.h>

// LearnableFiltration: out[b,i,j] = softplus( relu( relu( w_i*W1[0] + w_j*W1[1]
//   + d_ij*W1[2] + b1 ) @ W2 + b2 ) @ W3 + b3 )
// B=4, N=1024, H=32. Output [B,N,N] fp32 (4,194,304 elems).
//
// Inputs (metadata order):
//   0: weights   [B,N]      f32
//   1: distances [B,N,N]    f32
//   2: W1        [3,H]      f32
//   3: b1        [H]        f32
//   4: W2        [H,H]      f32
//   5: b2        [H]        f32
//   6: W3        [H,1]      f32
//   7: b3        [1]        f32

#define NB   4
#define NN   1024
#define NH   32
#define EPT  4      // elements (j's) per thread
#define TPB  256    // threads per block; TPB*EPT == NN

// ---- packed f32x2 helpers (FFMA2 is PTX-only; ptxas never auto-fuses) ----
__device__ __forceinline__ unsigned long long pack2(float lo, float hi) {
    unsigned long long r;
    asm("mov.b64 %0, {%1, %2};" : "=l"(r) : "f"(lo), "f"(hi));
    return r;
}
__device__ __forceinline__ void unpack2(unsigned long long v, float& lo, float& hi) {
    asm("mov.b64 {%0, %1}, %2;" : "=f"(lo), "=f"(hi) : "l"(v));
}
__device__ __forceinline__ void ffma2(unsigned long long& d,
                                      unsigned long long a,
                                      unsigned long long b) {
    asm("fma.rn.f32x2 %0, %1, %2, %0;" : "+l"(d) : "l"(a), "l"(b));
}

__global__ void __launch_bounds__(TPB)
lf_kernel(const float* __restrict__ weights,
          const float* __restrict__ distances,
          const float* __restrict__ W1,
          const float* __restrict__ b1,
          const float* __restrict__ W2,
          const float* __restrict__ b2,
          const float* __restrict__ W3,
          const float* __restrict__ b3,
          float* __restrict__ out)
{
    __shared__ float sAi[NH];        // w_i*W1[0][h] + b1[h]
    __shared__ float sW11[NH];       // W1[1][h]
    __shared__ float sW12[NH];       // W1[2][h]
    __shared__ float sB2[NH];
    __shared__ float sW3[NH];
    __shared__ float sW2[NH * NH];   // W2[h][k], row-major
    __shared__ float sWj[NN];        // weights[b, :]
    __shared__ float sB3;

    const int b   = blockIdx.x >> 10;         // blockIdx.x = b*1024 + i
    const int i   = blockIdx.x & (NN - 1);
    const int tid = threadIdx.x;

    for (int j = tid; j < NN; j += TPB) sWj[j] = weights[b * NN + j];
    for (int x = tid; x < NH * NH; x += TPB) sW2[x] = W2[x];
    if (tid < NH) {
        const float wi = weights[b * NN + i];
        sAi[tid]  = fmaf(wi, W1[tid], b1[tid]);  // W1[0][h]
        sW11[tid] = W1[NH + tid];                // W1[1][h]
        sW12[tid] = W1[2 * NH + tid];            // W1[2][h]
        sB2[tid]  = b2[tid];
        sW3[tid]  = W3[tid];
    }
    if (tid == 0) sB3 = b3[0];
    __syncthreads();

    const int    j0    = tid * EPT;
    const size_t rbase = ((size_t)b * NN + i) * NN + j0;

    // distances for the 4 contiguous j's (coalesced float4)
    const float4 dv = *reinterpret_cast<const float4*>(&distances[rbase]);
    float d[EPT] = {dv.x, dv.y, dv.z, dv.w};
    float wj[EPT];
#pragma unroll
    for (int e = 0; e < EPT; e++) wj[e] = sWj[j0 + e];

    // layer-2 accumulators: EPT elements x 32 channels, packed as f32x2
    unsigned long long acc[EPT][NH / 2];
#pragma unroll
    for (int e = 0; e < EPT; e++)
#pragma unroll
        for (int k = 0; k < NH / 2; k++) acc[e][k] = 0ull;

    for (int h = 0; h < NH; h++) {
        const float ai  = sAi[h];
        const float w11 = sW11[h];
        const float w12 = sW12[h];

        unsigned long long hv[EPT];
#pragma unroll
        for (int e = 0; e < EPT; e++) {
            float v = fmaxf(fmaf(d[e], w12, fmaf(wj[e], w11, ai)), 0.0f);
            hv[e] = pack2(v, v);
        }

        const float4* row = reinterpret_cast<const float4*>(&sW2[h * NH]);
#pragma unroll
        for (int q = 0; q < NH / 4; q++) {
            const float4 w = row[q];
            const unsigned long long w01 = pack2(w.x, w.y);
            const unsigned long long w23 = pack2(w.z, w.w);
#pragma unroll
            for (int e = 0; e < EPT; e++) {
                ffma2(acc[e][2 * q],     hv[e], w01);
                ffma2(acc[e][2 * q + 1], hv[e], w23);
            }
        }
    }

    // layer 3 + softplus
    const float b3v = sB3;
    float res[EPT];
#pragma unroll
    for (int e = 0; e < EPT; e++) {
        float s = 0.0f;
#pragma unroll
        for (int k = 0; k < NH / 2; k++) {
            float lo, hi;
            unpack2(acc[e][k], lo, hi);
            lo = fmaxf(lo + sB2[2 * k],     0.0f);
            hi = fmaxf(hi + sB2[2 * k + 1], 0.0f);
            s = fmaf(lo, sW3[2 * k],     s);
            s = fmaf(hi, sW3[2 * k + 1], s);
        }
        const float x = s + b3v;
        // numerically-stable softplus: max(x,0) + log1p(exp(-|x|))
        res[e] = fmaxf(x, 0.0f) + log1pf(expf(-fabsf(x)));
    }

    float4 ov = make_float4(res[0], res[1], res[2], res[3]);
    *reinterpret_cast<float4*>(&out[rbase]) = ov;
}

extern "C" void kernel_launch(void* const* d_in, const int* in_sizes, int n_in,
                              void* d_out, int out_size)
{
    const float* weights   = (const float*)d_in[0];
    const float* distances = (const float*)d_in[1];
    const float* W1        = (const float*)d_in[2];
    const float* b1        = (const float*)d_in[3];
    const float* W2        = (const float*)d_in[4];
    const float* b2        = (const float*)d_in[5];
    const float* W3        = (const float*)d_in[6];
    const float* b3        = (const float*)d_in[7];
    float* out             = (float*)d_out;

    dim3 grid(NB * NN);   // one block per (b, i)
    dim3 block(TPB);
    lf_kernel<<<grid, block>>>(weights, distances, W1, b1, W2, b2, W3, b3, out);
}

// round 3
// speedup vs baseline: 1.9157x; 1.9157x over previous
#include <cuda_runtime.h>
#include <cstdint>

// LearnableFiltration via legacy tensor-core mma.sync (tf32) — the harness
// targets .target sm_103 (family, no 'a'), so tcgen05 is unavailable; HMMA is.
//
// out[b,i,j] = softplus( relu( relu(H1) @ W2 + b2 ) @ W3 + b3 )
// H1[j,h] = wi*W1[0,h] + wj*W1[1,h] + d_ij*W1[2,h] + b1[h]
// B=4, N=1024, H=32.
//
// Inputs: 0 weights[B,N] 1 distances[B,N,N] 2 W1[3,H] 3 b1[H] 4 W2[H,H]
//         5 b2[H] 6 W3[H,1] 7 b3[1]  (all f32). Output [B,N,N] f32.

#define NB    4
#define NN    1024
#define NH    32
#define TPB   128                        // 4 warps / block
#define GRID  444                        // persistent; ~3 blocks/SM
#define NWT   (NB * NN * (NN / 16))      // warp-tiles of 16 j's: 262144

static __device__ __forceinline__ uint32_t to_tf32(float x) {
    uint32_t r;
    asm("cvt.rna.tf32.f32 %0, %1;" : "=r"(r) : "f"(x));
    return r;
}

// D += A(m16k8,row) * B(k8n8,col); tf32 in, f32 accum
static __device__ __forceinline__ void mma_tf32(float* d, const uint32_t* a,
                                                const uint32_t* b) {
    asm volatile(
        "mma.sync.aligned.m16n8k8.row.col.f32.tf32.tf32.f32 "
        "{%0,%1,%2,%3}, {%4,%5,%6,%7}, {%8,%9}, {%0,%1,%2,%3};"
        : "+f"(d[0]), "+f"(d[1]), "+f"(d[2]), "+f"(d[3])
        : "r"(a[0]), "r"(a[1]), "r"(a[2]), "r"(a[3]), "r"(b[0]), "r"(b[1]));
}

__global__ void __launch_bounds__(TPB)
lf_mma_kernel(const float* __restrict__ weights,
              const float* __restrict__ distances,
              const float* __restrict__ W1,
              const float* __restrict__ b1,
              const float* __restrict__ W2,
              const float* __restrict__ b2,
              const float* __restrict__ W3,
              const float* __restrict__ b3,
              float* __restrict__ out)
{
    __shared__ float  sW[NB * NN];    // all weights (16 KB)
    __shared__ float4 sW1[NH];        // {W1[0,h], W1[1,h], W1[2,h], b1[h]}
    __shared__ float2 sBW[NH];        // {b2[k], W3[k]}
    __shared__ float  sW2[NH * NH];   // W2[h][n] row-major

    const int tid  = threadIdx.x;
    const int wid  = tid >> 5;
    const int lane = tid & 31;
    const int q    = lane & 3;        // thread-in-group (k / col pos)
    const int g    = lane >> 2;       // group id (row pos)

    for (int x = tid; x < (NB * NN) / 4; x += TPB)
        ((float4*)sW)[x] = ((const float4*)weights)[x];
    for (int x = tid; x < (NH * NH) / 4; x += TPB)
        ((float4*)sW2)[x] = ((const float4*)W2)[x];
    if (tid < NH) {
        sW1[tid] = make_float4(W1[tid], W1[NH + tid], W1[2 * NH + tid], b1[tid]);
        sBW[tid] = make_float2(b2[tid], W3[tid]);
    }
    __syncthreads();

    // ---- per-thread loop-invariant fragments (registers) ----
    // B fragments: b[kt][nt][{k=q, k=q+4}] = tf32(W2[k + 8kt][n = g + 8nt])
    uint32_t bf[4][4][2];
#pragma unroll
    for (int kt = 0; kt < 4; kt++)
#pragma unroll
        for (int nt = 0; nt < 4; nt++) {
            bf[kt][nt][0] = to_tf32(sW2[(kt * 8 + q) * NH + nt * 8 + g]);
            bf[kt][nt][1] = to_tf32(sW2[(kt * 8 + q + 4) * NH + nt * 8 + g]);
        }
    // W1 columns this thread uses: h = q + {0,4} + 8*kt
    float4 w1c[8];
#pragma unroll
    for (int kt = 0; kt < 4; kt++) {
        w1c[2 * kt]     = sW1[8 * kt + q];
        w1c[2 * kt + 1] = sW1[8 * kt + q + 4];
    }
    // (b2, W3) at this thread's D columns: n = 8*nt + 2q + {0,1}
    float2 bw[8];
#pragma unroll
    for (int nt = 0; nt < 4; nt++) {
        bw[2 * nt]     = sBW[8 * nt + 2 * q];
        bw[2 * nt + 1] = sBW[8 * nt + 2 * q + 1];
    }
    const float b3v = b3[0];

    const int gw     = blockIdx.x * 4 + wid;
    const int stride = GRID * 4;

    // prefetch first tile's distances
    float d0 = 0.f, d1 = 0.f;
    if (gw < NWT) {
        const int bi = gw >> 6;
        const int j0 = (gw & 63) << 4;
        const size_t rb = ((size_t)bi << 10) + j0 + g;
        d0 = distances[rb];
        d1 = distances[rb + 8];
    }

    for (int t = gw; t < NWT; t += stride) {
        const int bi = t >> 6;              // b*1024 + i
        const int j0 = (t & 63) << 4;
        const int bb = bi >> 10;

        const float wi  = sW[bi];
        const float wj0 = sW[(bb << 10) + j0 + g];
        const float wj1 = sW[(bb << 10) + j0 + g + 8];

        // ---- A fragments: H1 rows {g, g+8}, cols q + {0,4} + 8kt ----
        uint32_t af[4][4];
#pragma unroll
        for (int kt = 0; kt < 4; kt++) {
            const float4 cA = w1c[2 * kt];       // col q + 8kt
            const float4 cB = w1c[2 * kt + 1];   // col q + 4 + 8kt
            float tA0 = fmaf(cA.z, d0, fmaf(cA.y, wj0, fmaf(cA.x, wi, cA.w)));
            float tA1 = fmaf(cA.z, d1, fmaf(cA.y, wj1, fmaf(cA.x, wi, cA.w)));
            float tB0 = fmaf(cB.z, d0, fmaf(cB.y, wj0, fmaf(cB.x, wi, cB.w)));
            float tB1 = fmaf(cB.z, d1, fmaf(cB.y, wj1, fmaf(cB.x, wi, cB.w)));
            af[kt][0] = to_tf32(fmaxf(tA0, 0.f));
            af[kt][1] = to_tf32(fmaxf(tA1, 0.f));
            af[kt][2] = to_tf32(fmaxf(tB0, 0.f));
            af[kt][3] = to_tf32(fmaxf(tB1, 0.f));
        }

        // prefetch next tile's distances (hide LDG under mma + epilogue)
        const int tn = t + stride;
        float d0n = 0.f, d1n = 0.f;
        if (tn < NWT) {
            const int bin = tn >> 6;
            const int j0n = (tn & 63) << 4;
            const size_t rbn = ((size_t)bin << 10) + j0n + g;
            d0n = distances[rbn];
            d1n = distances[rbn + 8];
        }

        // ---- 16 HMMAs: D[16x32] += A[16x8] @ B[8x8] ----
        float acc[4][4];
#pragma unroll
        for (int nt = 0; nt < 4; nt++)
#pragma unroll
            for (int r = 0; r < 4; r++) acc[nt][r] = 0.f;
#pragma unroll
        for (int kt = 0; kt < 4; kt++)
#pragma unroll
            for (int nt = 0; nt < 4; nt++)
                mma_tf32(acc[nt], af[kt], bf[kt][nt]);

        // ---- epilogue: relu(+b2) . W3, quad reduce, softplus ----
        float s0 = 0.f, s1 = 0.f;
#pragma unroll
        for (int nt = 0; nt < 4; nt++) {
            const float2 p0 = bw[2 * nt];
            const float2 p1 = bw[2 * nt + 1];
            s0 = fmaf(fmaxf(acc[nt][0] + p0.x, 0.f), p0.y, s0);
            s0 = fmaf(fmaxf(acc[nt][1] + p1.x, 0.f), p1.y, s0);
            s1 = fmaf(fmaxf(acc[nt][2] + p0.x, 0.f), p0.y, s1);
            s1 = fmaf(fmaxf(acc[nt][3] + p1.x, 0.f), p1.y, s1);
        }
        s0 += __shfl_xor_sync(0xffffffffu, s0, 1);
        s0 += __shfl_xor_sync(0xffffffffu, s0, 2);
        s1 += __shfl_xor_sync(0xffffffffu, s1, 1);
        s1 += __shfl_xor_sync(0xffffffffu, s1, 2);

        if (q == 0) {
            const float x0 = s0 + b3v;
            const float x1 = s1 + b3v;
            const float p0 = fmaxf(x0, 0.f) + log1pf(expf(-fabsf(x0)));
            const float p1 = fmaxf(x1, 0.f) + log1pf(expf(-fabsf(x1)));
            const size_t ob = ((size_t)bi << 10) + j0 + g;
            out[ob]     = p0;
            out[ob + 8] = p1;
        }

        d0 = d0n;
        d1 = d1n;
    }
}

extern "C" void kernel_launch(void* const* d_in, const int* in_sizes, int n_in,
                              void* d_out, int out_size)
{
    const float* weights   = (const float*)d_in[0];
    const float* distances = (const float*)d_in[1];
    const float* W1        = (const float*)d_in[2];
    const float* b1        = (const float*)d_in[3];
    const float* W2        = (const float*)d_in[4];
    const float* b2        = (const float*)d_in[5];
    const float* W3        = (const float*)d_in[6];
    const float* b3        = (const float*)d_in[7];
    float* out             = (float*)d_out;

    lf_mma_kernel<<<GRID, TPB>>>(weights, distances, W1, b1, W2, b2, W3, b3, out);
}